// round 9
// baseline (speedup 1.0000x reference)
#include <cuda_runtime.h>
#include <cuda_fp16.h>
#include <cstdint>

#define B_    8
#define CIN   320
#define COUT  320
#define H_    64
#define W_    64
#define KTOT  2880      // k = tap*320 + ci (tap-major)
#define BM    320
#define BK    64        // 4 mma k16 steps per stage; tap constant per stage
#define NKI   45
#define S_    2         // h rows per CTA (BN = 128)
#define NTH   320       // 10 warps: 5 m-positions x 2 h sub-tiles, warp tile 64x64
#define NSTG  3

// __device__ scratch
__device__ __align__(16) __half g_xq3[(size_t)B_ * CIN * H_ * 3 * W_]; // pre-shifted acts
__device__ __align__(16) __half g_wh[(size_t)COUT * KTOT];             // weights [o][tap][ci]

// ---------------- helpers ----------------
__device__ __forceinline__ void cp_async16(uint32_t dst, const void* src, int nbytes) {
    asm volatile("cp.async.cg.shared.global [%0], [%1], 16, %2;\n"
                 :: "r"(dst), "l"(src), "r"(nbytes));
}
__device__ __forceinline__ void ldsm_x4(uint32_t* r, uint32_t addr) {
    asm volatile("ldmatrix.sync.aligned.m8n8.x4.shared.b16 {%0,%1,%2,%3}, [%4];"
                 : "=r"(r[0]), "=r"(r[1]), "=r"(r[2]), "=r"(r[3]) : "r"(addr));
}
__device__ __forceinline__ void ldsm_x4t(uint32_t* r, uint32_t addr) {
    asm volatile("ldmatrix.sync.aligned.m8n8.x4.trans.shared.b16 {%0,%1,%2,%3}, [%4];"
                 : "=r"(r[0]), "=r"(r[1]), "=r"(r[2]), "=r"(r[3]) : "r"(addr));
}
__device__ __forceinline__ void hmma(float* d, const uint32_t* a, const uint32_t* b) {
    asm volatile("mma.sync.aligned.m16n8k16.row.col.f32.f16.f16.f32 "
                 "{%0,%1,%2,%3}, {%4,%5,%6,%7}, {%8,%9}, {%0,%1,%2,%3};"
                 : "+f"(d[0]), "+f"(d[1]), "+f"(d[2]), "+f"(d[3])
                 : "r"(a[0]), "r"(a[1]), "r"(a[2]), "r"(a[3]), "r"(b[0]), "r"(b[1]));
}
__device__ __forceinline__ uint32_t swz(uint32_t row, uint32_t byte_in_row) {
    return row * 128 + (byte_in_row ^ ((row & 7) << 4));
}

// ---------------- Prep 1: quantize + 3-shift; one warp per TWO (b,ci,h) rows --------
__global__ void quant_kernel(const float* __restrict__ x,
                             const float* __restrict__ inv_p,
                             const float* __restrict__ zp_p)
{
    const float inv = inv_p[0];
    const float zp  = zp_p[0];
    int wrp  = (blockIdx.x * blockDim.x + threadIdx.x) >> 5;  // row-pair index
    int lane = threadIdx.x & 31;
    size_t row0 = (size_t)wrp * 2;
    if (row0 >= (size_t)B_ * CIN * H_) return;

    uint32_t* g32 = reinterpret_cast<uint32_t*>(g_xq3);
    #pragma unroll
    for (int rr = 0; rr < 2; rr++) {
        size_t row = row0 + rr;
        float2 v = reinterpret_cast<const float2*>(x + row * W_)[lane];
        float r0 = fminf(fmaxf(rintf(v.x * inv) + zp, -128.f), 127.f) - zp;
        float r1 = fminf(fmaxf(rintf(v.y * inv) + zp, -128.f), 127.f) - zp;
        __half2 h01 = __floats2half2_rn(r0, r1);
        uint32_t r = *reinterpret_cast<uint32_t*>(&h01);

        uint32_t prev = __shfl_up_sync(0xffffffffu, r, 1);
        uint32_t next = __shfl_down_sync(0xffffffffu, r, 1);
        if (lane == 0)  prev = 0;
        if (lane == 31) next = 0;
        uint32_t v0 = (prev >> 16) | (r << 16);
        uint32_t v2 = (r >> 16) | (next << 16);

        size_t base = row * 96 + lane;
        g32[base]      = v0;
        g32[base + 32] = r;
        g32[base + 64] = v2;
    }
}

// ---------------- Prep 2: weights i32 [O][Ci][3][3] -> fp16 [O][tap][Ci] -------------
__global__ void wreorder_kernel(const int* __restrict__ w)
{
    const int o  = blockIdx.x;
    const int ci = threadIdx.x;
    const int* src = w + ((size_t)o * CIN + ci) * 9;
    __half* dst = g_wh + (size_t)o * KTOT + ci;
    #pragma unroll
    for (int tap = 0; tap < 9; tap++)
        dst[tap * CIN] = __int2half_rn(src[tap]);
}

// ---------------- Main fp16 HMMA implicit-GEMM conv ----------------
static constexpr int A_STG = BM * 128;            // 40960
static constexpr int B_STG = S_ * 64 * 128;       // 16384
static constexpr int STG   = A_STG + B_STG;       // 57344
static constexpr int SMEM_TOTAL = NSTG * STG;     // 172032

__global__ __launch_bounds__(NTH, 1)
void conv_hmma_kernel(const float* __restrict__ scale,
                      const float* __restrict__ bias,
                      float* __restrict__ out)
{
    extern __shared__ __align__(128) unsigned char sm[];
    const uint32_t smb = (uint32_t)__cvta_generic_to_shared(sm);

    const int tid  = threadIdx.x;
    const int warp = tid >> 5;             // 0..9
    const int lane = tid & 31;
    const int wm   = (warp >> 1) * 64;     // 0,64,128,192,256
    const int ws   = warp & 1;             // h sub-tile

    const int b  = blockIdx.x >> 5;
    const int hg = (blockIdx.x & 31) * S_;

    float acc[4][8][4];                    // [m16 tile][n8 group][frag]
    #pragma unroll
    for (int mt = 0; mt < 4; mt++)
        #pragma unroll
        for (int nt = 0; nt < 8; nt++)
            #pragma unroll
            for (int r = 0; r < 4; r++)
                acc[mt][nt][r] = 0.f;

    auto load_stage = [&](int it) {
        const int kb  = it * BK;
        const int tap = kb / 320;
        const int cib = kb - tap * 320;
        const int kh  = tap / 3;
        const int kw  = tap - kh * 3;
        const uint32_t base = smb + (it % NSTG) * STG;
        // A: 320 rows x 128B (2560 x 16B = 8 per thread)
        #pragma unroll
        for (int t = 0; t < 8; t++) {
            int idx = tid + t * NTH;
            int row = idx >> 3, vec = idx & 7;
            const void* src = g_wh + (size_t)row * KTOT + kb + vec * 8;
            cp_async16(base + swz(row, vec * 16), src, 16);
        }
        // B: 2 sub x 64 k-rows x 128B (1024 x 16B)
        #pragma unroll
        for (int t = 0; t < 4; t++) {
            int idx = tid + t * NTH;
            if (idx < 1024) {
                int ridx = idx >> 3, vec = idx & 7;
                int s = ridx >> 6, k = ridx & 63;
                int ci = cib + k;
                int ih = hg + s + kh - 1;
                int ok = ((unsigned)ih < (unsigned)H_) ? 16 : 0;
                if (!ok) ih = 0;
                const void* src = g_xq3 +
                    ((((size_t)b * CIN + ci) * H_ + ih) * 3 + kw) * W_ + vec * 8;
                cp_async16(base + A_STG + swz(s * 64 + k, vec * 16), src, ok);
            }
        }
        asm volatile("cp.async.commit_group;\n" ::: "memory");
    };

    load_stage(0);
    load_stage(1);

    const uint32_t a_row  = wm + (lane & 15);
    const uint32_t a_byte = (lane >> 4) * 16;
    const uint32_t b_krow = lane & 15;
    const uint32_t b_nby  = (lane >> 4) * 16;

    for (int it = 0; it < NKI; it++) {
        if (it + 1 < NKI) asm volatile("cp.async.wait_group 1;\n" ::: "memory");
        else              asm volatile("cp.async.wait_group 0;\n" ::: "memory");
        __syncthreads();
        if (it + 2 < NKI) load_stage(it + 2);

        const uint32_t Ab = smb + (it % NSTG) * STG;
        const uint32_t Bb = Ab + A_STG + ws * (64 * 128);
        #pragma unroll
        for (int ks = 0; ks < 4; ks++) {
            uint32_t a[4][4];
            #pragma unroll
            for (int mt = 0; mt < 4; mt++)
                ldsm_x4(a[mt], Ab + swz(a_row + mt * 16, ks * 32 + a_byte));
            #pragma unroll
            for (int ng = 0; ng < 4; ng++) {
                uint32_t bfrag[4];
                ldsm_x4t(bfrag, Bb + swz(ks * 16 + b_krow, ng * 32 + b_nby));
                #pragma unroll
                for (int mt = 0; mt < 4; mt++) {
                    hmma(acc[mt][ng * 2 + 0], a[mt], bfrag + 0);
                    hmma(acc[mt][ng * 2 + 1], a[mt], bfrag + 2);
                }
            }
        }
    }

    // ---------------- epilogue (direct fragment -> gmem) ----------------
    const int h = hg + ws;
    #pragma unroll
    for (int mt = 0; mt < 4; mt++) {
        const int o0 = wm + mt * 16 + (lane >> 2);
        const int o1 = o0 + 8;
        const float sc0 = scale[o0];
        const float sc1 = scale[o1];
        const float bb0 = bias[o0];
        const float bb1 = bias[o1];
        #pragma unroll
        for (int nt = 0; nt < 8; nt++) {
            const int w = nt * 8 + (lane & 3) * 2;
            float2 v0, v1;
            v0.x = sc0 * acc[mt][nt][0] + bb0;
            v0.y = sc0 * acc[mt][nt][1] + bb0;
            v1.x = sc1 * acc[mt][nt][2] + bb1;
            v1.y = sc1 * acc[mt][nt][3] + bb1;
            size_t p0 = (((size_t)b * COUT + o0) * H_ + h) * W_ + w;
            size_t p1 = (((size_t)b * COUT + o1) * H_ + h) * W_ + w;
            *reinterpret_cast<float2*>(out + p0) = v0;
            *reinterpret_cast<float2*>(out + p1) = v1;
        }
    }
}

// ---------------- Launch ----------------
// Inputs: 0:x f32  1:weight_int i32  2:weight_sum (unused)  3:scale f32
//         4:act_scales_inv f32  5:act_zero_points f32  6:bias f32 ; out f32
extern "C" void kernel_launch(void* const* d_in, const int* in_sizes, int n_in,
                              void* d_out, int out_size)
{
    const float* x    = (const float*)d_in[0];
    const int*   wint = (const int*)  d_in[1];
    const float* scl  = (const float*)d_in[3];
    const float* inv  = (const float*)d_in[4];
    const float* zp   = (const float*)d_in[5];
    const float* bias = (const float*)d_in[6];
    float* out = (float*)d_out;

    cudaFuncSetAttribute(conv_hmma_kernel,
                         cudaFuncAttributeMaxDynamicSharedMemorySize, SMEM_TOTAL);

    {   // quantize + pre-shift (2 rows per warp)
        int pairs = B_ * CIN * H_ / 2;      // 81920 warps
        quant_kernel<<<pairs / 8, 256>>>(x, inv, zp);
    }
    {   // weights -> fp16, tap-major reorder
        wreorder_kernel<<<COUT, CIN>>>(wint);
    }
    {   // fp16 HMMA implicit GEMM
        conv_hmma_kernel<<<B_ * (H_ / S_), NTH, SMEM_TOTAL>>>(scl, bias, out);
    }
}

// round 10
// speedup vs baseline: 1.1469x; 1.1469x over previous
#include <cuda_runtime.h>
#include <cuda_fp16.h>
#include <cstdint>

#define B_    8
#define CIN   320
#define COUT  320
#define H_    64
#define W_    64
#define NPIX  32768     // B*H*W
#define KTOT  2880      // k = tap*320 + ci (tap-major)
#define BM    320
#define BN    128       // flat pixel tile
#define BK    64        // 4 mma k16 steps; tap constant per stage (64 | 320)
#define NKI   45
#define NTH   640       // 20 warps: 10 m-pos x 2 n-pos, warp tile 32x64
#define NSTG  3

// __device__ scratch
__device__ __align__(16) __half g_xh[(size_t)NPIX * CIN];      // NHWC fp16 acts (21MB)
__device__ __align__(16) __half g_wh[(size_t)COUT * KTOT];     // weights [o][tap][ci]

// ---------------- helpers ----------------
__device__ __forceinline__ void cp_async16(uint32_t dst, const void* src, int nbytes) {
    asm volatile("cp.async.cg.shared.global [%0], [%1], 16, %2;\n"
                 :: "r"(dst), "l"(src), "r"(nbytes));
}
__device__ __forceinline__ void ldsm_x4(uint32_t* r, uint32_t addr) {
    asm volatile("ldmatrix.sync.aligned.m8n8.x4.shared.b16 {%0,%1,%2,%3}, [%4];"
                 : "=r"(r[0]), "=r"(r[1]), "=r"(r[2]), "=r"(r[3]) : "r"(addr));
}
__device__ __forceinline__ void hmma(float* d, const uint32_t* a, uint32_t b0, uint32_t b1) {
    asm volatile("mma.sync.aligned.m16n8k16.row.col.f32.f16.f16.f32 "
                 "{%0,%1,%2,%3}, {%4,%5,%6,%7}, {%8,%9}, {%0,%1,%2,%3};"
                 : "+f"(d[0]), "+f"(d[1]), "+f"(d[2]), "+f"(d[3])
                 : "r"(a[0]), "r"(a[1]), "r"(a[2]), "r"(a[3]), "r"(b0), "r"(b1));
}
__device__ __forceinline__ uint32_t swz(uint32_t row, uint32_t byte_in_row) {
    return row * 128 + (byte_in_row ^ ((row & 7) << 4));
}

// ---------------- Prep 1: quantize f32 NCHW -> fp16 NHWC ----------------
// one block per (b,h); smem transpose [w][ci]
#define QSTR 330    // half stride per w row (conflict-free: 165 words, coprime 32)
__global__ void quant_nhwc_kernel(const float* __restrict__ x,
                                  const float* __restrict__ inv_p,
                                  const float* __restrict__ zp_p)
{
    __shared__ __half t[64 * QSTR];
    const float inv = inv_p[0];
    const float zp  = zp_p[0];
    const int tid = threadIdx.x;          // 0..255
    const int bh  = blockIdx.x;           // b*64 + h
    const int b   = bh >> 6, h = bh & 63;

    const int w  = tid & 63;
    const int cq = tid >> 6;               // 0..3
    #pragma unroll
    for (int i = 0; i < 80; i++) {
        int ci = i * 4 + cq;
        float v = x[(((size_t)b * CIN + ci) * H_ + h) * W_ + w];
        float q = fminf(fmaxf(rintf(v * inv) + zp, -128.f), 127.f) - zp;
        t[w * QSTR + ci] = __float2half_rn(q);
    }
    __syncthreads();

    // write out: 64 pixels x 320 halfs = 2560 x 16B chunks
    #pragma unroll
    for (int i = 0; i < 10; i++) {
        int chunk = tid + i * 256;
        int ww  = chunk / 40;
        int c16 = chunk % 40;              // 16B chunk = 8 halfs
        const uint32_t* sp = reinterpret_cast<const uint32_t*>(t) + (ww * QSTR + c16 * 8) / 2;
        uint4 v;
        v.x = sp[0]; v.y = sp[1]; v.z = sp[2]; v.w = sp[3];
        *reinterpret_cast<uint4*>(g_xh + ((size_t)bh * W_ + ww) * CIN + c16 * 8) = v;
    }
}

// ---------------- Prep 2: weights i32 [O][Ci][3][3] -> fp16 [O][tap][Ci] -------------
__global__ void wreorder_kernel(const int* __restrict__ w)
{
    const int o  = blockIdx.x;
    const int ci = threadIdx.x;
    const int* src = w + ((size_t)o * CIN + ci) * 9;
    __half* dst = g_wh + (size_t)o * KTOT + ci;
    #pragma unroll
    for (int tap = 0; tap < 9; tap++)
        dst[tap * CIN] = __int2half_rn(src[tap]);
}

// ---------------- Main fp16 HMMA implicit-GEMM conv ----------------
static constexpr int A_STG = BM * 128;            // 40960
static constexpr int B_STG = BN * 128;            // 16384
static constexpr int STG   = A_STG + B_STG;       // 57344
static constexpr int SMEM_TOTAL = NSTG * STG;     // 172032

__global__ __launch_bounds__(NTH, 1)
void conv_hmma_kernel(const float* __restrict__ scale,
                      const float* __restrict__ bias,
                      float* __restrict__ out)
{
    extern __shared__ __align__(128) unsigned char sm[];
    const uint32_t smb = (uint32_t)__cvta_generic_to_shared(sm);

    const int tid  = threadIdx.x;
    const int warp = tid >> 5;             // 0..19
    const int lane = tid & 31;
    const int wm   = (warp >> 1) * 32;     // 0..288
    const int wn   = (warp & 1) * 64;      // 0/64

    const int n0 = blockIdx.x * BN;        // flat pixel base

    float acc[2][8][4];
    #pragma unroll
    for (int mt = 0; mt < 2; mt++)
        #pragma unroll
        for (int nt = 0; nt < 8; nt++)
            #pragma unroll
            for (int r = 0; r < 4; r++)
                acc[mt][nt][r] = 0.f;

    auto load_stage = [&](int it) {
        const int kb  = it * BK;
        const int tap = kb / 320;
        const int cib = kb - tap * 320;
        const int kh  = tap / 3;
        const int kw  = tap - kh * 3;
        const int dp  = (kh - 1) * W_ + (kw - 1);   // pixel delta when in-range
        const uint32_t base = smb + (it % NSTG) * STG;
        // A: 320 rows x 128B (2560 x 16B = 4 per thread)
        #pragma unroll
        for (int t = 0; t < 4; t++) {
            int idx = tid + t * NTH;
            int row = idx >> 3, vec = idx & 7;
            const void* src = g_wh + (size_t)row * KTOT + kb + vec * 8;
            cp_async16(base + swz(row, vec * 16), src, 16);
        }
        // B: 128 n-rows x 128B (1024 x 16B); row = pixel, zero-fill at borders
        #pragma unroll
        for (int t = 0; t < 2; t++) {
            int idx = tid + t * NTH;
            if (idx < 1024) {
                int row = idx >> 3, vec = idx & 7;
                int n   = n0 + row;
                int rem = n & 4095;
                int h   = rem >> 6, w = rem & 63;
                int ih  = h + kh - 1;
                int iw  = w + kw - 1;
                bool okb = ((unsigned)ih < (unsigned)H_) && ((unsigned)iw < (unsigned)W_);
                size_t p = okb ? (size_t)(n + dp) : 0;
                const void* src = g_xh + p * CIN + cib + vec * 8;
                cp_async16(base + A_STG + swz(row, vec * 16), src, okb ? 16 : 0);
            }
        }
        asm volatile("cp.async.commit_group;\n" ::: "memory");
    };

    load_stage(0);
    load_stage(1);

    const uint32_t a_row  = wm + (lane & 15);
    const uint32_t b_row  = wn + (lane & 15);
    const uint32_t hi16   = (lane >> 4) * 16;

    for (int it = 0; it < NKI; it++) {
        if (it + 1 < NKI) asm volatile("cp.async.wait_group 1;\n" ::: "memory");
        else              asm volatile("cp.async.wait_group 0;\n" ::: "memory");
        __syncthreads();
        if (it + 2 < NKI) load_stage(it + 2);

        const uint32_t Ab = smb + (it % NSTG) * STG;
        const uint32_t Bb = Ab + A_STG;
        #pragma unroll
        for (int ks = 0; ks < 4; ks++) {
            uint32_t a[2][4];
            #pragma unroll
            for (int mt = 0; mt < 2; mt++)
                ldsm_x4(a[mt], Ab + swz(a_row + mt * 16, ks * 32 + hi16));
            #pragma unroll
            for (int p = 0; p < 4; p++) {
                uint32_t bf[4];   // m0=n0-7/k0-7, m1=n8-15/k0-7, m2=n0-7/k8-15, m3=n8-15/k8-15
                ldsm_x4(bf, Bb + swz(b_row + p * 16, ks * 32 + hi16));
                #pragma unroll
                for (int mt = 0; mt < 2; mt++) {
                    hmma(acc[mt][p * 2 + 0], a[mt], bf[0], bf[2]);
                    hmma(acc[mt][p * 2 + 1], a[mt], bf[1], bf[3]);
                }
            }
        }
    }

    // ---------------- epilogue (direct fragment -> gmem, flat n) ----------------
    #pragma unroll
    for (int mt = 0; mt < 2; mt++) {
        const int o0 = wm + mt * 16 + (lane >> 2);
        const int o1 = o0 + 8;
        const float sc0 = scale[o0];
        const float sc1 = scale[o1];
        const float bb0 = bias[o0];
        const float bb1 = bias[o1];
        #pragma unroll
        for (int nt = 0; nt < 8; nt++) {
            const int n   = n0 + wn + nt * 8 + (lane & 3) * 2;  // even -> pair same (b,h)
            const int b   = n >> 12;
            const int rem = n & 4095;
            float2 v0, v1;
            v0.x = sc0 * acc[mt][nt][0] + bb0;
            v0.y = sc0 * acc[mt][nt][1] + bb0;
            v1.x = sc1 * acc[mt][nt][2] + bb1;
            v1.y = sc1 * acc[mt][nt][3] + bb1;
            size_t p0 = ((size_t)b * COUT + o0) * 4096 + rem;
            size_t p1 = ((size_t)b * COUT + o1) * 4096 + rem;
            *reinterpret_cast<float2*>(out + p0) = v0;
            *reinterpret_cast<float2*>(out + p1) = v1;
        }
    }
}

// ---------------- Launch ----------------
// Inputs: 0:x f32  1:weight_int i32  2:weight_sum (unused)  3:scale f32
//         4:act_scales_inv f32  5:act_zero_points f32  6:bias f32 ; out f32
extern "C" void kernel_launch(void* const* d_in, const int* in_sizes, int n_in,
                              void* d_out, int out_size)
{
    const float* x    = (const float*)d_in[0];
    const int*   wint = (const int*)  d_in[1];
    const float* scl  = (const float*)d_in[3];
    const float* inv  = (const float*)d_in[4];
    const float* zp   = (const float*)d_in[5];
    const float* bias = (const float*)d_in[6];
    float* out = (float*)d_out;

    cudaFuncSetAttribute(conv_hmma_kernel,
                         cudaFuncAttributeMaxDynamicSharedMemorySize, SMEM_TOTAL);

    {   // quantize -> NHWC fp16 (single copy)
        quant_nhwc_kernel<<<B_ * H_, 256>>>(x, inv, zp);
    }
    {   // weights -> fp16, tap-major reorder
        wreorder_kernel<<<COUT, CIN>>>(wint);
    }
    {   // fp16 HMMA implicit GEMM, flat-n tiles
        conv_hmma_kernel<<<NPIX / BN, NTH, SMEM_TOTAL>>>(scl, bias, out);
    }
}